// round 1
// baseline (speedup 1.0000x reference)
#include <cuda_runtime.h>
#include <math.h>

// Problem constants (match reference)
#define NN 50000
#define EE 600000
#define FF 128
#define HH 128
#define CC 16
#define GG 500

// ---------------- scratch (device globals; no allocation allowed) ------------
__device__ int   g_indeg[NN];
__device__ int   g_cursor[NN];
__device__ int   g_off[NN + 1];
__device__ float g_dis[NN];
__device__ int   g_csr_src[EE];
__device__ float g_csr_w[EE];
__device__ float g_h1[(size_t)NN * HH];   // x @ W1
__device__ float g_a1[(size_t)NN * HH];   // relu(aggregate(h1) + b1)
__device__ float g_h2[(size_t)NN * CC];   // a1 @ W2
__device__ float g_pool[GG * CC];
__device__ float g_cnt[GG];

// ---------------- init: zero accumulators ------------------------------------
__global__ void k_init() {
    int i = blockIdx.x * blockDim.x + threadIdx.x;
    if (i < NN) { g_indeg[i] = 0; g_cursor[i] = 0; }
    if (i < GG * CC) g_pool[i] = 0.0f;
    if (i < GG) g_cnt[i] = 0.0f;
}

// ---------------- degree count (in-degree at dst) -----------------------------
__global__ void k_deg(const int* __restrict__ dst) {
    int e = blockIdx.x * blockDim.x + threadIdx.x;
    if (e < EE) atomicAdd(&g_indeg[dst[e]], 1);
}

__global__ void k_dis() {
    int i = blockIdx.x * blockDim.x + threadIdx.x;
    if (i < NN) g_dis[i] = rsqrtf((float)g_indeg[i] + 1.0f);  // +1 = self loop
}

// ---------------- exclusive scan of indeg -> off (single block) ---------------
__global__ void k_scan() {
    __shared__ int sums[1024];
    const int CH = (NN + 1023) / 1024;  // 49
    int t = threadIdx.x;
    int base = t * CH;
    int s = 0;
    for (int j = 0; j < CH; j++) {
        int idx = base + j;
        if (idx < NN) s += g_indeg[idx];
    }
    sums[t] = s;
    __syncthreads();
    // Hillis-Steele inclusive scan
    for (int d = 1; d < 1024; d <<= 1) {
        int v = (t >= d) ? sums[t - d] : 0;
        __syncthreads();
        sums[t] += v;
        __syncthreads();
    }
    int run = (t == 0) ? 0 : sums[t - 1];
    for (int j = 0; j < CH; j++) {
        int idx = base + j;
        if (idx < NN) {
            g_off[idx] = run;
            run += g_indeg[idx];
        }
    }
    if (t == 1023) g_off[NN] = sums[1023];
}

// ---------------- fill CSR (counting-sort placement) ---------------------------
__global__ void k_csr(const int* __restrict__ src, const int* __restrict__ dst) {
    int e = blockIdx.x * blockDim.x + threadIdx.x;
    if (e < EE) {
        int d = dst[e];
        int sN = src[e];
        int p = g_off[d] + atomicAdd(&g_cursor[d], 1);
        g_csr_src[p] = sN;
        g_csr_w[p]   = g_dis[sN] * g_dis[d];
    }
}

// ---------------- GEMM1: g_h1 = x @ W1 (N x 128 @ 128 x 128, fp32) -------------
// 64x128 tile per block, 256 threads (16x16), 4x8 register tile, BK=32
__global__ __launch_bounds__(256) void k_gemm1(const float* __restrict__ x,
                                               const float* __restrict__ W1) {
    __shared__ float As[64][33];       // padded
    __shared__ float Bs[32][132];      // padded (keeps 16B alignment)
    const int tid = threadIdx.x;
    const int tx = tid & 15;           // 0..15 -> cols tx*8..tx*8+7
    const int ty = tid >> 4;           // 0..15 -> rows ty*4..ty*4+3
    const int m0 = blockIdx.x * 64;

    float acc[4][8];
#pragma unroll
    for (int r = 0; r < 4; r++)
#pragma unroll
        for (int u = 0; u < 8; u++) acc[r][u] = 0.0f;

    for (int k0 = 0; k0 < 128; k0 += 32) {
        // load As: 64 rows x 32 cols = 512 float4, 2 per thread
#pragma unroll
        for (int it = 0; it < 2; it++) {
            int idx = tid + it * 256;       // 0..511
            int r   = idx >> 3;             // row 0..63
            int c4  = idx & 7;              // float4 col 0..7
            float4 v = make_float4(0.f, 0.f, 0.f, 0.f);
            int row = m0 + r;
            if (row < NN) v = *(const float4*)(x + (size_t)row * 128 + k0 + c4 * 4);
            As[r][c4 * 4 + 0] = v.x;
            As[r][c4 * 4 + 1] = v.y;
            As[r][c4 * 4 + 2] = v.z;
            As[r][c4 * 4 + 3] = v.w;
        }
        // load Bs: 32 rows x 128 cols = 1024 float4, 4 per thread
#pragma unroll
        for (int it = 0; it < 4; it++) {
            int idx = tid + it * 256;       // 0..1023
            int r   = idx >> 5;             // k row 0..31
            int c4  = idx & 31;             // float4 col 0..31
            float4 v = *(const float4*)(W1 + (size_t)(k0 + r) * 128 + c4 * 4);
            *(float4*)&Bs[r][c4 * 4] = v;
        }
        __syncthreads();

#pragma unroll
        for (int k = 0; k < 32; k++) {
            float a[4], b[8];
#pragma unroll
            for (int r = 0; r < 4; r++) a[r] = As[ty * 4 + r][k];
#pragma unroll
            for (int u = 0; u < 8; u++) b[u] = Bs[k][tx * 8 + u];
#pragma unroll
            for (int r = 0; r < 4; r++)
#pragma unroll
                for (int u = 0; u < 8; u++) acc[r][u] = fmaf(a[r], b[u], acc[r][u]);
        }
        __syncthreads();
    }

#pragma unroll
    for (int r = 0; r < 4; r++) {
        int row = m0 + ty * 4 + r;
        if (row < NN) {
            float4 v0 = make_float4(acc[r][0], acc[r][1], acc[r][2], acc[r][3]);
            float4 v1 = make_float4(acc[r][4], acc[r][5], acc[r][6], acc[r][7]);
            *(float4*)&g_h1[(size_t)row * 128 + tx * 8]     = v0;
            *(float4*)&g_h1[(size_t)row * 128 + tx * 8 + 4] = v1;
        }
    }
}

// ---------------- aggregation layer 1 (gather, 128 feat/node) ------------------
__global__ __launch_bounds__(128) void k_agg1(const float* __restrict__ b1) {
    const int t = threadIdx.x;   // feature
    const int i = blockIdx.x;    // node
    const float di = g_dis[i];
    float acc = g_h1[(size_t)i * 128 + t] * (di * di);   // self loop
    const int s0 = g_off[i];
    const int s1 = g_off[i + 1];
    int j = s0;
    for (; j + 1 < s1; j += 2) {
        int   sA = g_csr_src[j];
        int   sB = g_csr_src[j + 1];
        float wA = g_csr_w[j];
        float wB = g_csr_w[j + 1];
        float hA = g_h1[(size_t)sA * 128 + t];
        float hB = g_h1[(size_t)sB * 128 + t];
        acc = fmaf(hA, wA, acc);
        acc = fmaf(hB, wB, acc);
    }
    if (j < s1) {
        acc = fmaf(g_h1[(size_t)g_csr_src[j] * 128 + t], g_csr_w[j], acc);
    }
    g_a1[(size_t)i * 128 + t] = fmaxf(acc + b1[t], 0.0f);
}

// ---------------- GEMM2: g_h2 = a1 @ W2 (N x 128 @ 128 x 16) -------------------
__global__ __launch_bounds__(256) void k_gemm2(const float* __restrict__ W2) {
    __shared__ float Ws[128 * 16];
    const int tid = threadIdx.x;
#pragma unroll
    for (int it = 0; it < 8; it++) Ws[tid + it * 256] = W2[tid + it * 256];
    __syncthreads();

    int gid = blockIdx.x * 256 + tid;       // < N*C exactly (50000*16/256 = 3125 blocks)
    int i = gid >> 4;
    int c = gid & 15;
    const float* row = &g_a1[(size_t)i * 128];
    float acc = 0.0f;
#pragma unroll 8
    for (int k = 0; k < 128; k++) acc = fmaf(row[k], Ws[k * 16 + c], acc);
    g_h2[(size_t)i * 16 + c] = acc;
}

// ---------------- aggregation layer 2 + mean-pool scatter ----------------------
__global__ __launch_bounds__(128) void k_agg2_pool(const float* __restrict__ b2,
                                                   const int* __restrict__ batch) {
    const int tid  = threadIdx.x;
    const int lane = tid & 15;                        // class
    const int i    = blockIdx.x * 8 + (tid >> 4);     // node
    if (i >= NN) return;
    const float di = g_dis[i];
    float acc = g_h2[(size_t)i * 16 + lane] * (di * di);
    const int s0 = g_off[i];
    const int s1 = g_off[i + 1];
    for (int j = s0; j < s1; j++) {
        acc = fmaf(g_h2[(size_t)g_csr_src[j] * 16 + lane], g_csr_w[j], acc);
    }
    acc += b2[lane];
    int b = batch[i];
    atomicAdd(&g_pool[b * 16 + lane], acc);
    if (lane == 0) atomicAdd(&g_cnt[b], 1.0f);
}

// ---------------- mean + log_softmax -------------------------------------------
__global__ __launch_bounds__(256) void k_out(float* __restrict__ out) {
    const int tid = threadIdx.x;
    const int c = tid & 15;
    const int r = blockIdx.x * 16 + (tid >> 4);
    float v = 0.0f;
    if (r < GG) v = g_pool[r * 16 + c] / fmaxf(g_cnt[r], 1.0f);
    float m = v;
#pragma unroll
    for (int k = 8; k; k >>= 1) m = fmaxf(m, __shfl_xor_sync(0xffffffffu, m, k, 16));
    float e = expf(v - m);
    float s = e;
#pragma unroll
    for (int k = 8; k; k >>= 1) s += __shfl_xor_sync(0xffffffffu, s, k, 16);
    if (r < GG) out[r * 16 + c] = v - m - logf(s);
}

// -------------------------------------------------------------------------------
extern "C" void kernel_launch(void* const* d_in, const int* in_sizes, int n_in,
                              void* d_out, int out_size) {
    const float* x   = (const float*)d_in[0];   // [N, 128]
    const float* W1  = (const float*)d_in[1];   // [128, 128]
    const float* b1  = (const float*)d_in[2];   // [128]
    const float* W2  = (const float*)d_in[3];   // [128, 16]
    const float* b2  = (const float*)d_in[4];   // [16]
    const int* esrc  = (const int*)d_in[5];     // [E]
    const int* edst  = (const int*)d_in[6];     // [E]
    const int* batch = (const int*)d_in[7];     // [N]
    float* out = (float*)d_out;                 // [G, 16]

    k_init<<<(NN + 255) / 256, 256>>>();
    k_deg<<<(EE + 255) / 256, 256>>>(edst);
    k_dis<<<(NN + 255) / 256, 256>>>();
    k_scan<<<1, 1024>>>();
    k_csr<<<(EE + 255) / 256, 256>>>(esrc, edst);

    k_gemm1<<<(NN + 63) / 64, 256>>>(x, W1);
    k_agg1<<<NN, 128>>>(b1);
    k_gemm2<<<(NN * CC) / 256, 256>>>(W2);
    k_agg2_pool<<<(NN + 7) / 8, 128>>>(b2, batch);
    k_out<<<(GG + 15) / 16, 256>>>(out);
}

// round 2
// speedup vs baseline: 1.4081x; 1.4081x over previous
#include <cuda_runtime.h>
#include <math.h>

// Problem constants (match reference)
#define NN 50000
#define EE 600000
#define FF 128
#define HH 128
#define CC 16
#define GG 500
#define NB 196   // ceil(NN/256)

// ---------------- scratch (device globals; no allocation allowed) ------------
__device__ int   g_indeg[NN];
__device__ int   g_cursor[NN];
__device__ int   g_off[NN + 1];
__device__ float g_dis[NN];
__device__ int   g_bsum[NB];
__device__ int   g_base[NB];
__device__ int2  g_csr[EE];               // {src, __float_as_int(weight)}
__device__ float g_h1[(size_t)NN * HH];   // x @ W1
__device__ float g_a1[(size_t)NN * HH];   // relu(aggregate(h1) + b1)
__device__ float g_h2[(size_t)NN * CC];   // a1 @ W2
__device__ float g_pool[GG * CC];
__device__ float g_cnt[GG];

// ---------------- init: zero accumulators ------------------------------------
__global__ void k_init() {
    int i = blockIdx.x * blockDim.x + threadIdx.x;
    if (i < NN) { g_indeg[i] = 0; g_cursor[i] = 0; }
    if (i < GG * CC) g_pool[i] = 0.0f;
    if (i < GG) g_cnt[i] = 0.0f;
}

// ---------------- degree count (in-degree at dst) -----------------------------
__global__ void k_deg(const int* __restrict__ dst) {
    int e = blockIdx.x * blockDim.x + threadIdx.x;
    if (e < EE) atomicAdd(&g_indeg[dst[e]], 1);
}

// ---------------- scan phase 1: per-block scan + dis --------------------------
__global__ __launch_bounds__(256) void k_part() {
    const int t = threadIdx.x;
    const int i = blockIdx.x * 256 + t;
    int v = (i < NN) ? g_indeg[i] : 0;
    if (i < NN) g_dis[i] = rsqrtf((float)v + 1.0f);   // +1 = self loop

    // block-wide inclusive scan (warp shuffles)
    const int lane = t & 31, w = t >> 5;
    int x = v;
#pragma unroll
    for (int d = 1; d < 32; d <<= 1) {
        int y = __shfl_up_sync(0xffffffffu, x, d);
        if (lane >= d) x += y;
    }
    __shared__ int wsum[8];
    if (lane == 31) wsum[w] = x;
    __syncthreads();
    if (t < 8) {
        int y = wsum[t];
#pragma unroll
        for (int d = 1; d < 8; d <<= 1) {
            int z = __shfl_up_sync(0xffu, y, d);
            if (t >= d) y += z;
        }
        wsum[t] = y;
    }
    __syncthreads();
    int incl = x + ((w > 0) ? wsum[w - 1] : 0);
    if (i < NN) g_off[i] = incl - v;        // local exclusive
    if (t == 255) g_bsum[blockIdx.x] = incl;
}

// ---------------- scan phase 2: scan the 196 block sums -----------------------
__global__ __launch_bounds__(256) void k_scanb() {
    const int t = threadIdx.x;
    int v = (t < NB) ? g_bsum[t] : 0;
    const int lane = t & 31, w = t >> 5;
    int x = v;
#pragma unroll
    for (int d = 1; d < 32; d <<= 1) {
        int y = __shfl_up_sync(0xffffffffu, x, d);
        if (lane >= d) x += y;
    }
    __shared__ int wsum[8];
    if (lane == 31) wsum[w] = x;
    __syncthreads();
    if (t < 8) {
        int y = wsum[t];
#pragma unroll
        for (int d = 1; d < 8; d <<= 1) {
            int z = __shfl_up_sync(0xffu, y, d);
            if (t >= d) y += z;
        }
        wsum[t] = y;
    }
    __syncthreads();
    int incl = x + ((w > 0) ? wsum[w - 1] : 0);
    if (t < NB) g_base[t] = incl - v;       // exclusive base per block
}

// ---------------- scan phase 3: add bases --------------------------------------
__global__ void k_fin() {
    int i = blockIdx.x * blockDim.x + threadIdx.x;
    if (i < NN) g_off[i] += g_base[i >> 8];
    if (i == 0) g_off[NN] = EE;
}

// ---------------- fill CSR (counting-sort placement) ---------------------------
__global__ void k_csr(const int* __restrict__ src, const int* __restrict__ dst) {
    int e = blockIdx.x * blockDim.x + threadIdx.x;
    if (e < EE) {
        int d = dst[e];
        int sN = src[e];
        int p = g_off[d] + atomicAdd(&g_cursor[d], 1);
        g_csr[p] = make_int2(sN, __float_as_int(g_dis[sN] * g_dis[d]));
    }
}

// ---------------- GEMM1: g_h1 = x @ W1 (N x 128 @ 128 x 128, fp32) -------------
__global__ __launch_bounds__(256) void k_gemm1(const float* __restrict__ x,
                                               const float* __restrict__ W1) {
    __shared__ float As[64][33];
    __shared__ float Bs[32][132];
    const int tid = threadIdx.x;
    const int tx = tid & 15;
    const int ty = tid >> 4;
    const int m0 = blockIdx.x * 64;

    float acc[4][8];
#pragma unroll
    for (int r = 0; r < 4; r++)
#pragma unroll
        for (int u = 0; u < 8; u++) acc[r][u] = 0.0f;

    for (int k0 = 0; k0 < 128; k0 += 32) {
#pragma unroll
        for (int it = 0; it < 2; it++) {
            int idx = tid + it * 256;
            int r   = idx >> 3;
            int c4  = idx & 7;
            float4 v = make_float4(0.f, 0.f, 0.f, 0.f);
            int row = m0 + r;
            if (row < NN) v = *(const float4*)(x + (size_t)row * 128 + k0 + c4 * 4);
            As[r][c4 * 4 + 0] = v.x;
            As[r][c4 * 4 + 1] = v.y;
            As[r][c4 * 4 + 2] = v.z;
            As[r][c4 * 4 + 3] = v.w;
        }
#pragma unroll
        for (int it = 0; it < 4; it++) {
            int idx = tid + it * 256;
            int r   = idx >> 5;
            int c4  = idx & 31;
            float4 v = *(const float4*)(W1 + (size_t)(k0 + r) * 128 + c4 * 4);
            *(float4*)&Bs[r][c4 * 4] = v;
        }
        __syncthreads();

#pragma unroll
        for (int k = 0; k < 32; k++) {
            float a[4], b[8];
#pragma unroll
            for (int r = 0; r < 4; r++) a[r] = As[ty * 4 + r][k];
#pragma unroll
            for (int u = 0; u < 8; u++) b[u] = Bs[k][tx * 8 + u];
#pragma unroll
            for (int r = 0; r < 4; r++)
#pragma unroll
                for (int u = 0; u < 8; u++) acc[r][u] = fmaf(a[r], b[u], acc[r][u]);
        }
        __syncthreads();
    }

#pragma unroll
    for (int r = 0; r < 4; r++) {
        int row = m0 + ty * 4 + r;
        if (row < NN) {
            float4 v0 = make_float4(acc[r][0], acc[r][1], acc[r][2], acc[r][3]);
            float4 v1 = make_float4(acc[r][4], acc[r][5], acc[r][6], acc[r][7]);
            *(float4*)&g_h1[(size_t)row * 128 + tx * 8]     = v0;
            *(float4*)&g_h1[(size_t)row * 128 + tx * 8 + 4] = v1;
        }
    }
}

// ---------------- aggregation layer 1: warp-per-node, float4 -------------------
__global__ __launch_bounds__(256) void k_agg1(const float* __restrict__ b1) {
    const int gw   = (blockIdx.x * 256 + threadIdx.x) >> 5;   // node
    const int lane = threadIdx.x & 31;                         // float4 feature chunk
    if (gw >= NN) return;
    const float4* __restrict__ h1 = (const float4*)g_h1;

    const float di = g_dis[gw];
    const float w0 = di * di;
    float4 a = h1[(size_t)gw * 32 + lane];
    float4 acc = make_float4(a.x * w0, a.y * w0, a.z * w0, a.w * w0);

    int j = g_off[gw];
    const int e = g_off[gw + 1];
    for (; j + 1 < e; j += 2) {
        int2 c0 = g_csr[j];
        int2 c1 = g_csr[j + 1];
        float4 hA = h1[(size_t)c0.x * 32 + lane];
        float4 hB = h1[(size_t)c1.x * 32 + lane];
        float wA = __int_as_float(c0.y);
        float wB = __int_as_float(c1.y);
        acc.x = fmaf(hA.x, wA, acc.x);
        acc.y = fmaf(hA.y, wA, acc.y);
        acc.z = fmaf(hA.z, wA, acc.z);
        acc.w = fmaf(hA.w, wA, acc.w);
        acc.x = fmaf(hB.x, wB, acc.x);
        acc.y = fmaf(hB.y, wB, acc.y);
        acc.z = fmaf(hB.z, wB, acc.z);
        acc.w = fmaf(hB.w, wB, acc.w);
    }
    if (j < e) {
        int2 c0 = g_csr[j];
        float4 hA = h1[(size_t)c0.x * 32 + lane];
        float wA = __int_as_float(c0.y);
        acc.x = fmaf(hA.x, wA, acc.x);
        acc.y = fmaf(hA.y, wA, acc.y);
        acc.z = fmaf(hA.z, wA, acc.z);
        acc.w = fmaf(hA.w, wA, acc.w);
    }
    float4 bb = ((const float4*)b1)[lane];
    float4 o = make_float4(fmaxf(acc.x + bb.x, 0.0f), fmaxf(acc.y + bb.y, 0.0f),
                           fmaxf(acc.z + bb.z, 0.0f), fmaxf(acc.w + bb.w, 0.0f));
    ((float4*)g_a1)[(size_t)gw * 32 + lane] = o;
}

// ---------------- GEMM2: g_h2 = a1 @ W2 (N x 128 @ 128 x 16) -------------------
__global__ __launch_bounds__(256) void k_gemm2(const float* __restrict__ W2) {
    __shared__ float WsT[16][132];   // transposed, padded
    const int tid = threadIdx.x;
#pragma unroll
    for (int it = 0; it < 8; it++) {
        int idx = tid + it * 256;    // k*16 + c
        int k = idx >> 4, c = idx & 15;
        WsT[c][k] = W2[idx];
    }
    __syncthreads();

    int gid = blockIdx.x * 256 + tid;   // exact: 50000*16 / 256 = 3125 blocks
    int i = gid >> 4;
    int c = gid & 15;
    const float4* __restrict__ row = (const float4*)(g_a1 + (size_t)i * 128);
    const float*  wt = WsT[c];
    float acc = 0.0f;
#pragma unroll
    for (int k4 = 0; k4 < 32; k4++) {
        float4 a = row[k4];
        float4 w = *(const float4*)(wt + k4 * 4);
        acc = fmaf(a.x, w.x, acc);
        acc = fmaf(a.y, w.y, acc);
        acc = fmaf(a.z, w.z, acc);
        acc = fmaf(a.w, w.w, acc);
    }
    g_h2[(size_t)i * 16 + c] = acc;
}

// ---------------- aggregation layer 2 + mean-pool scatter ----------------------
__global__ __launch_bounds__(128) void k_agg2_pool(const float* __restrict__ b2,
                                                   const int* __restrict__ batch) {
    const int tid  = threadIdx.x;
    const int lane = tid & 15;                        // class
    const int i    = blockIdx.x * 8 + (tid >> 4);     // node
    if (i >= NN) return;
    const float di = g_dis[i];
    float acc = g_h2[(size_t)i * 16 + lane] * (di * di);
    const int s0 = g_off[i];
    const int s1 = g_off[i + 1];
    for (int j = s0; j < s1; j++) {
        int2 c0 = g_csr[j];
        acc = fmaf(g_h2[(size_t)c0.x * 16 + lane], __int_as_float(c0.y), acc);
    }
    acc += b2[lane];
    int b = batch[i];
    atomicAdd(&g_pool[b * 16 + lane], acc);
    if (lane == 0) atomicAdd(&g_cnt[b], 1.0f);
}

// ---------------- mean + log_softmax -------------------------------------------
__global__ __launch_bounds__(256) void k_out(float* __restrict__ out) {
    const int tid = threadIdx.x;
    const int c = tid & 15;
    const int r = blockIdx.x * 16 + (tid >> 4);
    float v = 0.0f;
    if (r < GG) v = g_pool[r * 16 + c] / fmaxf(g_cnt[r], 1.0f);
    float m = v;
#pragma unroll
    for (int k = 8; k; k >>= 1) m = fmaxf(m, __shfl_xor_sync(0xffffffffu, m, k, 16));
    float e = expf(v - m);
    float s = e;
#pragma unroll
    for (int k = 8; k; k >>= 1) s += __shfl_xor_sync(0xffffffffu, s, k, 16);
    if (r < GG) out[r * 16 + c] = v - m - logf(s);
}

// -------------------------------------------------------------------------------
extern "C" void kernel_launch(void* const* d_in, const int* in_sizes, int n_in,
                              void* d_out, int out_size) {
    const float* x   = (const float*)d_in[0];   // [N, 128]
    const float* W1  = (const float*)d_in[1];   // [128, 128]
    const float* b1  = (const float*)d_in[2];   // [128]
    const float* W2  = (const float*)d_in[3];   // [128, 16]
    const float* b2  = (const float*)d_in[4];   // [16]
    const int* esrc  = (const int*)d_in[5];     // [E]
    const int* edst  = (const int*)d_in[6];     // [E]
    const int* batch = (const int*)d_in[7];     // [N]
    float* out = (float*)d_out;                 // [G, 16]

    k_init<<<(NN + 255) / 256, 256>>>();
    k_deg<<<(EE + 255) / 256, 256>>>(edst);
    k_part<<<NB, 256>>>();
    k_scanb<<<1, 256>>>();
    k_fin<<<NB, 256>>>();
    k_csr<<<(EE + 255) / 256, 256>>>(esrc, edst);

    k_gemm1<<<(NN + 63) / 64, 256>>>(x, W1);
    k_agg1<<<(NN * 32 + 255) / 256, 256>>>(b1);
    k_gemm2<<<(NN * CC) / 256, 256>>>(W2);
    k_agg2_pool<<<(NN + 7) / 8, 128>>>(b2, batch);
    k_out<<<(GG + 15) / 16, 256>>>(out);
}

// round 4
// speedup vs baseline: 1.9219x; 1.3649x over previous
#include <cuda_runtime.h>
#include <cuda_fp16.h>
#include <cstdint>
#include <math.h>

#define NN 50000
#define EE 600000
#define FF 128
#define HH 128
#define CC 16
#define GG 500
#define NB 196   // ceil(NN/256)

// ---------------- scratch --------------------------------------------------
__device__ int    g_indeg[NN];
__device__ int    g_cursor[NN];
__device__ int    g_off[NN + 1];
__device__ float  g_dis[NN];
__device__ int    g_bsum[NB];
__device__ int2   g_csr[EE];                    // {src, weight bits}
__device__ __half g_h1h[(size_t)NN * HH];       // x @ W1  (fp16)
__device__ float  g_a1[(size_t)NN * HH];        // relu(agg(h1) + b1) fp32
__device__ float  g_h2[(size_t)NN * CC];
__device__ float  g_pool[GG * CC];
__device__ float  g_cnt[GG];

// ---------------- init ------------------------------------------------------
__global__ void k_init() {
    int i = blockIdx.x * blockDim.x + threadIdx.x;
    if (i < NN) { g_indeg[i] = 0; g_cursor[i] = 0; }
    if (i < GG * CC) g_pool[i] = 0.0f;
    if (i < GG) g_cnt[i] = 0.0f;
}

// ---------------- degree ----------------------------------------------------
__global__ void k_deg(const int* __restrict__ dst) {
    int e = blockIdx.x * blockDim.x + threadIdx.x;
    if (e < EE) atomicAdd(&g_indeg[dst[e]], 1);
}

// ---------------- scan phase 1: per-block scan + dis -------------------------
__global__ __launch_bounds__(256) void k_part() {
    const int t = threadIdx.x;
    const int i = blockIdx.x * 256 + t;
    int v = (i < NN) ? g_indeg[i] : 0;
    if (i < NN) g_dis[i] = rsqrtf((float)v + 1.0f);   // +1 = self loop

    const int lane = t & 31, w = t >> 5;
    int x = v;
#pragma unroll
    for (int d = 1; d < 32; d <<= 1) {
        int y = __shfl_up_sync(0xffffffffu, x, d);
        if (lane >= d) x += y;
    }
    __shared__ int wsum[8];
    if (lane == 31) wsum[w] = x;
    __syncthreads();
    if (t < 8) {
        int y = wsum[t];
#pragma unroll
        for (int d = 1; d < 8; d <<= 1) {
            int z = __shfl_up_sync(0xffu, y, d);
            if (t >= d) y += z;
        }
        wsum[t] = y;
    }
    __syncthreads();
    int incl = x + ((w > 0) ? wsum[w - 1] : 0);
    if (i < NN) g_off[i] = incl - v;
    if (t == 255) g_bsum[blockIdx.x] = incl;
}

// ---------------- scan phase 2+3 fused: per-block base reduce + add ----------
__global__ __launch_bounds__(256) void k_fin() {
    const int t = threadIdx.x;
    const int bid = blockIdx.x;
    int s = (t < bid) ? g_bsum[t] : 0;            // bid <= 195 < 256
    const int lane = t & 31, w = t >> 5;
#pragma unroll
    for (int d = 16; d; d >>= 1) s += __shfl_xor_sync(0xffffffffu, s, d);
    __shared__ int ws[8];
    if (lane == 0) ws[w] = s;
    __syncthreads();
    __shared__ int base;
    if (t == 0) {
        int b = 0;
#pragma unroll
        for (int j = 0; j < 8; j++) b += ws[j];
        base = b;
    }
    __syncthreads();
    int i = bid * 256 + t;
    if (i < NN) g_off[i] += base;
    if (bid == 0 && t == 0) g_off[NN] = EE;
}

// ---------------- CSR fill ---------------------------------------------------
__global__ void k_csr(const int* __restrict__ src, const int* __restrict__ dst) {
    int e = blockIdx.x * blockDim.x + threadIdx.x;
    if (e < EE) {
        int d = dst[e];
        int sN = src[e];
        int p = g_off[d] + atomicAdd(&g_cursor[d], 1);
        g_csr[p] = make_int2(sN, __float_as_int(g_dis[sN] * g_dis[d]));
    }
}

// ---------------- GEMM1: h1 = fp16( x @ W1 ), tensor cores --------------------
// block: 256 thr (8 warps), tile M=128 x N=128, K staged in halves of 64.
#define LDH 72   // halves per smem row (64 used + 8 pad); 144B stride
__global__ __launch_bounds__(256) void k_gemm1(const float* __restrict__ x,
                                               const float* __restrict__ W1) {
    __shared__ __half As[128][LDH];   // x tile (row, k)
    __shared__ __half Bs[128][LDH];   // W1^T tile (n, k)
    const int tid  = threadIdx.x;
    const int wid  = tid >> 5;
    const int lane = tid & 31;
    const int g    = lane >> 2;          // 0..7
    const int q    = lane & 3;           // 0..3
    const int m0   = blockIdx.x * 128;
    const int mw   = wid * 16;           // warp row base within tile

    float acc[16][4];
#pragma unroll
    for (int n = 0; n < 16; n++)
#pragma unroll
        for (int c = 0; c < 4; c++) acc[n][c] = 0.0f;

    for (int k0 = 0; k0 < 128; k0 += 64) {
        // load x tile half-K: 128 rows x 16 float4
#pragma unroll
        for (int it = 0; it < 8; it++) {
            int idx = it * 256 + tid;          // 0..2047
            int r   = idx >> 4;                // row 0..127
            int c4  = idx & 15;                // float4 col 0..15
            float4 v = make_float4(0.f, 0.f, 0.f, 0.f);
            int row = m0 + r;
            if (row < NN) v = *(const float4*)(x + (size_t)row * 128 + k0 + c4 * 4);
            __half* p = &As[r][c4 * 4];
            *(__half2*)(p)     = __floats2half2_rn(v.x, v.y);
            *(__half2*)(p + 2) = __floats2half2_rn(v.z, v.w);
        }
        // load W1^T tile: Bs[n][k] from W1[k][n]
#pragma unroll
        for (int it = 0; it < 32; it++) {
            int idx = it * 256 + tid;          // 0..8191
            int kk  = idx >> 7;                // 0..63
            int n   = idx & 127;
            Bs[n][kk] = __float2half_rn(W1[(size_t)(k0 + kk) * 128 + n]);
        }
        __syncthreads();

#pragma unroll
        for (int ks = 0; ks < 4; ks++) {       // 4 x k16 steps
            int kc = ks * 16 + q * 2;
            unsigned int a0 = *(const unsigned int*)&As[mw + g][kc];
            unsigned int a1 = *(const unsigned int*)&As[mw + g + 8][kc];
            unsigned int a2 = *(const unsigned int*)&As[mw + g][kc + 8];
            unsigned int a3 = *(const unsigned int*)&As[mw + g + 8][kc + 8];
#pragma unroll
            for (int nt = 0; nt < 16; nt++) {
                unsigned int b0 = *(const unsigned int*)&Bs[nt * 8 + g][kc];
                unsigned int b1 = *(const unsigned int*)&Bs[nt * 8 + g][kc + 8];
                asm volatile(
                    "mma.sync.aligned.m16n8k16.row.col.f32.f16.f16.f32 "
                    "{%0,%1,%2,%3}, {%4,%5,%6,%7}, {%8,%9}, {%0,%1,%2,%3};"
                    : "+f"(acc[nt][0]), "+f"(acc[nt][1]),
                      "+f"(acc[nt][2]), "+f"(acc[nt][3])
                    : "r"(a0), "r"(a1), "r"(a2), "r"(a3), "r"(b0), "r"(b1));
            }
        }
        __syncthreads();
    }

    // epilogue: fp16 store
    const int r0 = m0 + mw + g;
#pragma unroll
    for (int nt = 0; nt < 16; nt++) {
        int n = nt * 8 + q * 2;
        if (r0 < NN)
            *(__half2*)&g_h1h[(size_t)r0 * 128 + n] = __floats2half2_rn(acc[nt][0], acc[nt][1]);
        if (r0 + 8 < NN)
            *(__half2*)&g_h1h[(size_t)(r0 + 8) * 128 + n] = __floats2half2_rn(acc[nt][2], acc[nt][3]);
    }
}

// ---------------- aggregation layer 1: warp/node, fp16 gathers ----------------
__device__ __forceinline__ float4 h4_to_f4(uint2 v) {
    float2 lo = __half22float2(*(__half2*)&v.x);
    float2 hi = __half22float2(*(__half2*)&v.y);
    return make_float4(lo.x, lo.y, hi.x, hi.y);
}

__global__ __launch_bounds__(256) void k_agg1(const float* __restrict__ b1) {
    const int gw   = (blockIdx.x * 256 + threadIdx.x) >> 5;   // node
    const int lane = threadIdx.x & 31;                         // 4-feat chunk
    if (gw >= NN) return;
    const uint2* __restrict__ h1 = (const uint2*)g_h1h;        // 4 halves each

    const float di = g_dis[gw];
    const float w0 = di * di;
    float4 a = h4_to_f4(h1[(size_t)gw * 32 + lane]);
    float4 acc = make_float4(a.x * w0, a.y * w0, a.z * w0, a.w * w0);

    int j = g_off[gw];
    const int e = g_off[gw + 1];
    for (; j + 1 < e; j += 2) {
        int2 c0 = g_csr[j];
        int2 c1 = g_csr[j + 1];
        float4 hA = h4_to_f4(h1[(size_t)c0.x * 32 + lane]);
        float4 hB = h4_to_f4(h1[(size_t)c1.x * 32 + lane]);
        float wA = __int_as_float(c0.y);
        float wB = __int_as_float(c1.y);
        acc.x = fmaf(hA.x, wA, acc.x); acc.y = fmaf(hA.y, wA, acc.y);
        acc.z = fmaf(hA.z, wA, acc.z); acc.w = fmaf(hA.w, wA, acc.w);
        acc.x = fmaf(hB.x, wB, acc.x); acc.y = fmaf(hB.y, wB, acc.y);
        acc.z = fmaf(hB.z, wB, acc.z); acc.w = fmaf(hB.w, wB, acc.w);
    }
    if (j < e) {
        int2 c0 = g_csr[j];
        float4 hA = h4_to_f4(h1[(size_t)c0.x * 32 + lane]);
        float wA = __int_as_float(c0.y);
        acc.x = fmaf(hA.x, wA, acc.x); acc.y = fmaf(hA.y, wA, acc.y);
        acc.z = fmaf(hA.z, wA, acc.z); acc.w = fmaf(hA.w, wA, acc.w);
    }
    float4 bb = ((const float4*)b1)[lane];
    float4 o = make_float4(fmaxf(acc.x + bb.x, 0.0f), fmaxf(acc.y + bb.y, 0.0f),
                           fmaxf(acc.z + bb.z, 0.0f), fmaxf(acc.w + bb.w, 0.0f));
    ((float4*)g_a1)[(size_t)gw * 32 + lane] = o;
}

// ---------------- GEMM2: h2 = a1 @ W2 -----------------------------------------
__global__ __launch_bounds__(256) void k_gemm2(const float* __restrict__ W2) {
    __shared__ float WsT[16][132];
    const int tid = threadIdx.x;
#pragma unroll
    for (int it = 0; it < 8; it++) {
        int idx = tid + it * 256;
        int k = idx >> 4, c = idx & 15;
        WsT[c][k] = W2[idx];
    }
    __syncthreads();

    int gid = blockIdx.x * 256 + tid;
    int i = gid >> 4;
    int c = gid & 15;
    const float4* __restrict__ row = (const float4*)(g_a1 + (size_t)i * 128);
    const float* wt = WsT[c];
    float acc = 0.0f;
#pragma unroll
    for (int k4 = 0; k4 < 32; k4++) {
        float4 a = row[k4];
        float4 w = *(const float4*)(wt + k4 * 4);
        acc = fmaf(a.x, w.x, acc);
        acc = fmaf(a.y, w.y, acc);
        acc = fmaf(a.z, w.z, acc);
        acc = fmaf(a.w, w.w, acc);
    }
    g_h2[(size_t)i * 16 + c] = acc;
}

// ---------------- aggregation layer 2 + mean pool -----------------------------
__global__ __launch_bounds__(128) void k_agg2_pool(const float* __restrict__ b2,
                                                   const int* __restrict__ batch) {
    const int tid  = threadIdx.x;
    const int lane = tid & 15;
    const int i    = blockIdx.x * 8 + (tid >> 4);
    if (i >= NN) return;
    const float di = g_dis[i];
    float acc = g_h2[(size_t)i * 16 + lane] * (di * di);
    const int s0 = g_off[i];
    const int s1 = g_off[i + 1];
    for (int j = s0; j < s1; j++) {
        int2 c0 = g_csr[j];
        acc = fmaf(g_h2[(size_t)c0.x * 16 + lane], __int_as_float(c0.y), acc);
    }
    acc += b2[lane];
    int b = batch[i];
    atomicAdd(&g_pool[b * 16 + lane], acc);
    if (lane == 0) atomicAdd(&g_cnt[b], 1.0f);
}

// ---------------- mean + log_softmax ------------------------------------------
__global__ __launch_bounds__(256) void k_out(float* __restrict__ out) {
    const int tid = threadIdx.x;
    const int c = tid & 15;
    const int r = blockIdx.x * 16 + (tid >> 4);
    float v = 0.0f;
    if (r < GG) v = g_pool[r * 16 + c] / fmaxf(g_cnt[r], 1.0f);
    float m = v;
#pragma unroll
    for (int k = 8; k; k >>= 1) m = fmaxf(m, __shfl_xor_sync(0xffffffffu, m, k, 16));
    float e = expf(v - m);
    float s = e;
#pragma unroll
    for (int k = 8; k; k >>= 1) s += __shfl_xor_sync(0xffffffffu, s, k, 16);
    if (r < GG) out[r * 16 + c] = v - m - logf(s);
}

// -------------------------------------------------------------------------------
extern "C" void kernel_launch(void* const* d_in, const int* in_sizes, int n_in,
                              void* d_out, int out_size) {
    const float* x   = (const float*)d_in[0];
    const float* W1  = (const float*)d_in[1];
    const float* b1  = (const float*)d_in[2];
    const float* W2  = (const float*)d_in[3];
    const float* b2  = (const float*)d_in[4];
    const int* esrc  = (const int*)d_in[5];
    const int* edst  = (const int*)d_in[6];
    const int* batch = (const int*)d_in[7];
    float* out = (float*)d_out;

    k_init<<<(NN + 255) / 256, 256>>>();
    k_deg<<<(EE + 255) / 256, 256>>>(edst);
    k_part<<<NB, 256>>>();
    k_fin<<<NB, 256>>>();
    k_csr<<<(EE + 255) / 256, 256>>>(esrc, edst);

    k_gemm1<<<(NN + 127) / 128, 256>>>(x, W1);
    k_agg1<<<(NN * 32 + 255) / 256, 256>>>(b1);
    k_gemm2<<<(NN * CC) / 256, 256>>>(W2);
    k_agg2_pool<<<(NN + 7) / 8, 128>>>(b2, batch);
    k_out<<<(GG + 15) / 16, 256>>>(out);
}